// round 14
// baseline (speedup 1.0000x reference)
#include <cuda_runtime.h>
#include <cuda_fp16.h>
#include <cstdint>

#define N_NODES 100000
#define N_EDGES 1600000
#define DIM     128
#define SCAN_BS 1024
#define NSCAN   ((N_NODES + SCAN_BS - 1) / SCAN_BS)   // 98

#define SCAT_BLOCKS ((N_EDGES / 4 + 255) / 256)        // 1563
#define CVT_BLOCKS  ((N_NODES * DIM / 8 + 255) / 256)  // 6250

// Scratch (no cudaMalloc allowed)
__device__ __half   g_agg16[(size_t)N_NODES * DIM];  // fp16 normalized aggregate
__device__ __half   g_h16[(size_t)N_NODES * DIM];    // fp16 h prescaled by norm[row]
__device__ int      g_deg[N_NODES];
__device__ float    g_norm[N_NODES];
__device__ int      g_part[N_NODES];
__device__ int      g_bsum[NSCAN];
__device__ int      g_row_start[N_NODES + 1];
__device__ int      g_cursor[N_NODES];
__device__ int      g_sorted_src[N_EDGES];

// ---------------------------------------------------------------------------
// 1. zero degree counters
// ---------------------------------------------------------------------------
__global__ void zero_deg_kernel() {
    int i = blockIdx.x * blockDim.x + threadIdx.x;
    if (i < N_NODES) g_deg[i] = 0;
}

// ---------------------------------------------------------------------------
// 2. in-degree histogram (4 edges per thread, int4 load)
// ---------------------------------------------------------------------------
__global__ void deg_kernel(const int* __restrict__ edge_dst) {
    int i = blockIdx.x * blockDim.x + threadIdx.x;
    if (i < N_EDGES / 4) {
        int4 d = __ldg(&((const int4*)edge_dst)[i]);
        atomicAdd(&g_deg[d.x], 1);
        atomicAdd(&g_deg[d.y], 1);
        atomicAdd(&g_deg[d.z], 1);
        atomicAdd(&g_deg[d.w], 1);
    }
}

// ---------------------------------------------------------------------------
// 3a. per-block exclusive scan of deg
// ---------------------------------------------------------------------------
__global__ __launch_bounds__(SCAN_BS)
void scan_block_kernel() {
    __shared__ int s[SCAN_BS];
    int tid = threadIdx.x;
    int gi  = blockIdx.x * SCAN_BS + tid;
    int v = (gi < N_NODES) ? g_deg[gi] : 0;
    s[tid] = v;
    __syncthreads();
#pragma unroll
    for (int off = 1; off < SCAN_BS; off <<= 1) {
        int t = (tid >= off) ? s[tid - off] : 0;
        __syncthreads();
        s[tid] += t;
        __syncthreads();
    }
    if (gi < N_NODES) g_part[gi] = s[tid] - v;
    if (tid == SCAN_BS - 1) g_bsum[blockIdx.x] = s[tid];
}

// ---------------------------------------------------------------------------
// 3b. finalize: re-scan block sums locally, build row_start/cursor/norm
// ---------------------------------------------------------------------------
__global__ __launch_bounds__(256)
void finalize_kernel() {
    __shared__ int ss[128];
    int tid = threadIdx.x;
    if (tid < 128) ss[tid] = (tid < NSCAN) ? g_bsum[tid] : 0;
    __syncthreads();
#pragma unroll
    for (int off = 1; off < 128; off <<= 1) {
        int t = (tid < 128 && tid >= off) ? ss[tid - off] : 0;
        __syncthreads();
        if (tid < 128) ss[tid] += t;
        __syncthreads();
    }
    int i = blockIdx.x * blockDim.x + tid;
    if (i < N_NODES) {
        int reg = i / SCAN_BS;
        int boff = (reg == 0) ? 0 : ss[reg - 1];
        int rs = g_part[i] + boff;
        g_row_start[i] = rs;
        g_cursor[i]    = rs;
        int d = g_deg[i];
        g_norm[i] = rsqrtf((float)(d > 0 ? d : 1));
    }
    if (i == 0) g_row_start[N_NODES] = N_EDGES;
}

// ---------------------------------------------------------------------------
// 4. FUSED: edge bucketing (4 edges/thread) + h -> prescaled fp16 conversion
// ---------------------------------------------------------------------------
__global__ __launch_bounds__(256)
void scatter_cvt_kernel(const float* __restrict__ h,
                        const int*   __restrict__ edge_src,
                        const int*   __restrict__ edge_dst) {
    int b = blockIdx.x;
    if (b < SCAT_BLOCKS) {
        int i = b * 256 + threadIdx.x;
        if (i < N_EDGES / 4) {
            int4 d = __ldg(&((const int4*)edge_dst)[i]);
            int4 s = __ldg(&((const int4*)edge_src)[i]);
            g_sorted_src[atomicAdd(&g_cursor[d.x], 1)] = s.x;
            g_sorted_src[atomicAdd(&g_cursor[d.y], 1)] = s.y;
            g_sorted_src[atomicAdd(&g_cursor[d.z], 1)] = s.z;
            g_sorted_src[atomicAdd(&g_cursor[d.w], 1)] = s.w;
        }
    } else {
        int i = (b - SCAT_BLOCKS) * 256 + threadIdx.x;   // over N*DIM/8
        if (i < N_NODES * DIM / 8) {
            float nr = __ldg(&g_norm[i >> 4]);
            const float4* h4 = (const float4*)h;
            float4 a = __ldg(&h4[i * 2]);
            float4 bb = __ldg(&h4[i * 2 + 1]);
            __half2 p0 = __floats2half2_rn(a.x * nr, a.y * nr);
            __half2 p1 = __floats2half2_rn(a.z * nr, a.w * nr);
            __half2 p2 = __floats2half2_rn(bb.x * nr, bb.y * nr);
            __half2 p3 = __floats2half2_rn(bb.z * nr, bb.w * nr);
            uint4 o;
            o.x = *(uint32_t*)&p0; o.y = *(uint32_t*)&p1;
            o.z = *(uint32_t*)&p2; o.w = *(uint32_t*)&p3;
            ((uint4*)g_h16)[i] = o;
        }
    }
}

// ---------------------------------------------------------------------------
// 5. gather: one warp per node, paired half-warps.
//    Half-warp (16 lanes x uint4 = 128 halves) covers a full row.
//    Lanes 0-15 take even edges, 16-31 odd edges; final shfl_xor(16) merge.
// ---------------------------------------------------------------------------
__global__ __launch_bounds__(256)
void gather_kernel() {
    int warp = (blockIdx.x * blockDim.x + threadIdx.x) >> 5;
    int lane = threadIdx.x & 31;
    if (warp >= N_NODES) return;

    int half = lane >> 4;       // 0 or 1
    int hl   = lane & 15;       // position in half-warp

    int start = __ldg(&g_row_start[warp]);
    int end   = __ldg(&g_row_start[warp + 1]);

    const uint4* h4 = (const uint4*)g_h16;   // 16 uint4 per row
    float acc[8];
#pragma unroll
    for (int j = 0; j < 8; j++) acc[j] = 0.f;

    int e = start;
    // 4 edges per iter (2 per half-warp)
    for (; e + 3 < end; e += 4) {
        int s0 = __ldg(&g_sorted_src[e + half]);
        int s1 = __ldg(&g_sorted_src[e + 2 + half]);
        uint4 u0 = __ldg(&h4[(size_t)s0 * 16 + hl]);
        uint4 u1 = __ldg(&h4[(size_t)s1 * 16 + hl]);
#pragma unroll
        for (int q = 0; q < 4; q++) {
            uint32_t w0 = (&u0.x)[q];
            uint32_t w1 = (&u1.x)[q];
            float2 f0 = __half22float2(*(__half2*)&w0);
            float2 f1 = __half22float2(*(__half2*)&w1);
            acc[q * 2]     += f0.x + f1.x;
            acc[q * 2 + 1] += f0.y + f1.y;
        }
    }
    // 2 edges (1 per half-warp)
    if (e + 1 < end) {
        int s0 = __ldg(&g_sorted_src[e + half]);
        uint4 u0 = __ldg(&h4[(size_t)s0 * 16 + hl]);
#pragma unroll
        for (int q = 0; q < 4; q++) {
            uint32_t w0 = (&u0.x)[q];
            float2 f0 = __half22float2(*(__half2*)&w0);
            acc[q * 2]     += f0.x;
            acc[q * 2 + 1] += f0.y;
        }
        e += 2;
    }
    // final single edge: half 0 only
    if (e < end && half == 0) {
        int s0 = __ldg(&g_sorted_src[e]);
        uint4 u0 = __ldg(&h4[(size_t)s0 * 16 + hl]);
#pragma unroll
        for (int q = 0; q < 4; q++) {
            uint32_t w0 = (&u0.x)[q];
            float2 f0 = __half22float2(*(__half2*)&w0);
            acc[q * 2]     += f0.x;
            acc[q * 2 + 1] += f0.y;
        }
    }

    // merge halves (each lane l gets acc[l] + acc[l^16])
#pragma unroll
    for (int j = 0; j < 8; j++)
        acc[j] += __shfl_xor_sync(0xFFFFFFFFu, acc[j], 16);

    if (half == 0) {
        float nd = __ldg(&g_norm[warp]);
        __half2 p0 = __floats2half2_rn(acc[0] * nd, acc[1] * nd);
        __half2 p1 = __floats2half2_rn(acc[2] * nd, acc[3] * nd);
        __half2 p2 = __floats2half2_rn(acc[4] * nd, acc[5] * nd);
        __half2 p3 = __floats2half2_rn(acc[6] * nd, acc[7] * nd);
        uint4 o;
        o.x = *(uint32_t*)&p0; o.y = *(uint32_t*)&p1;
        o.z = *(uint32_t*)&p2; o.w = *(uint32_t*)&p3;
        ((uint4*)g_agg16)[(size_t)warp * 16 + hl] = o;
    }
}

// ---------------------------------------------------------------------------
// 6. fp16 ldmatrix MMA GEMM: out = aggn @ W^T + b
//    m16n8k16, fp32 acc. 8 warps: 4m x 2n, warp tile 32x64.
// ---------------------------------------------------------------------------
#define SH_STRIDE 136
#define SMEM_HALF_W (128 * SH_STRIDE)                 // halves
#define SMEM_SZ (2 * SMEM_HALF_W * 2)                 // 69632 B

#define LDSM_X4(r0, r1, r2, r3, addr) \
    asm volatile("ldmatrix.sync.aligned.m8n8.x4.shared.b16 {%0,%1,%2,%3}, [%4];" \
        : "=r"(r0), "=r"(r1), "=r"(r2), "=r"(r3) : "r"(addr))

__global__ __launch_bounds__(256)
void mma_gemm_kernel(const float* __restrict__ W,
                     const float* __restrict__ bias,
                     float*       __restrict__ out) {
    extern __shared__ __half smh[];
    __half* sW = smh;                    // [n][k]
    __half* sA = smh + SMEM_HALF_W;      // [m][k]

    int tid  = threadIdx.x;
    int lane = tid & 31;
    int warp = tid >> 5;
    int wm   = warp & 3;      // m0 = wm*32
    int wn   = warp >> 2;     // n0 = wn*64
    int row0 = blockIdx.x * 128;

    // ---- stage W as fp16 ----
    {
        const float4* W4 = (const float4*)W;
#pragma unroll
        for (int t = tid; t < 4096; t += 256) {
            int n = t >> 5;
            int q = t & 31;
            float4 w = __ldg(&W4[n * 32 + q]);
            __half2 h0 = __floats2half2_rn(w.x, w.y);
            __half2 h1 = __floats2half2_rn(w.z, w.w);
            uint32_t* p = (uint32_t*)&sW[n * SH_STRIDE + q * 4];
            p[0] = *(uint32_t*)&h0;
            p[1] = *(uint32_t*)&h1;
        }
    }
    // ---- stage A (fp16 bit-copy) ----
    {
        const uint2* A2 = (const uint2*)g_agg16;
#pragma unroll
        for (int t = tid; t < 4096; t += 256) {
            int m = t >> 5;
            int q = t & 31;
            int row = row0 + m;
            uint2 a = make_uint2(0u, 0u);
            if (row < N_NODES) a = __ldg(&A2[(size_t)row * 32 + q]);
            uint32_t* p = (uint32_t*)&sA[m * SH_STRIDE + q * 4];
            p[0] = a.x;
            p[1] = a.y;
        }
    }
    __syncthreads();

    float acc[2][8][4];
#pragma unroll
    for (int mt = 0; mt < 2; mt++)
#pragma unroll
        for (int nt = 0; nt < 8; nt++)
#pragma unroll
            for (int c = 0; c < 4; c++) acc[mt][nt][c] = 0.f;

    uint32_t sA_base = (uint32_t)__cvta_generic_to_shared(sA);
    uint32_t sW_base = (uint32_t)__cvta_generic_to_shared(sW);

#pragma unroll
    for (int ks = 0; ks < 8; ks++) {
        int k0 = ks * 16;
        uint32_t a[2][4];
#pragma unroll
        for (int mt = 0; mt < 2; mt++) {
            int r = wm * 32 + mt * 16 + (lane & 15);
            int c = k0 + ((lane >> 4) << 3);
            uint32_t addr = sA_base + (uint32_t)(r * SH_STRIDE + c) * 2;
            LDSM_X4(a[mt][0], a[mt][1], a[mt][2], a[mt][3], addr);
        }
        uint32_t b[4][4];
#pragma unroll
        for (int p = 0; p < 4; p++) {
            int n = wn * 64 + p * 16 + ((lane >= 16) ? 8 : 0) + (lane & 7);
            int c = k0 + (((lane >> 3) & 1) << 3);
            uint32_t addr = sW_base + (uint32_t)(n * SH_STRIDE + c) * 2;
            LDSM_X4(b[p][0], b[p][1], b[p][2], b[p][3], addr);
        }
#pragma unroll
        for (int nt = 0; nt < 8; nt++) {
            uint32_t b0 = b[nt >> 1][(nt & 1) ? 2 : 0];
            uint32_t b1 = b[nt >> 1][(nt & 1) ? 3 : 1];
#pragma unroll
            for (int mt = 0; mt < 2; mt++) {
                asm volatile(
                    "mma.sync.aligned.m16n8k16.row.col.f32.f16.f16.f32 "
                    "{%0,%1,%2,%3}, {%4,%5,%6,%7}, {%8,%9}, {%0,%1,%2,%3};"
                    : "+f"(acc[mt][nt][0]), "+f"(acc[mt][nt][1]),
                      "+f"(acc[mt][nt][2]), "+f"(acc[mt][nt][3])
                    : "r"(a[mt][0]), "r"(a[mt][1]),
                      "r"(a[mt][2]), "r"(a[mt][3]),
                      "r"(b0), "r"(b1));
            }
        }
    }

    // ---- epilogue: bias + store ----
#pragma unroll
    for (int mt = 0; mt < 2; mt++) {
        int r0 = row0 + wm * 32 + mt * 16 + (lane >> 2);
        int r1 = r0 + 8;
#pragma unroll
        for (int nt = 0; nt < 8; nt++) {
            int c = wn * 64 + nt * 8 + (lane & 3) * 2;
            float2 bb = __ldg((const float2*)&bias[c]);
            if (r0 < N_NODES) {
                float2 o = make_float2(acc[mt][nt][0] + bb.x,
                                       acc[mt][nt][1] + bb.y);
                *(float2*)&out[(size_t)r0 * DIM + c] = o;
            }
            if (r1 < N_NODES) {
                float2 o = make_float2(acc[mt][nt][2] + bb.x,
                                       acc[mt][nt][3] + bb.y);
                *(float2*)&out[(size_t)r1 * DIM + c] = o;
            }
        }
    }
}

// ---------------------------------------------------------------------------
// Launch
// ---------------------------------------------------------------------------
extern "C" void kernel_launch(void* const* d_in, const int* in_sizes, int n_in,
                              void* d_out, int out_size) {
    const float* h        = (const float*)d_in[0];
    const float* W        = (const float*)d_in[1];
    const float* b        = (const float*)d_in[2];
    const int*   edge_src = (const int*)d_in[3];
    const int*   edge_dst = (const int*)d_in[4];
    float*       out      = (float*)d_out;

    zero_deg_kernel<<<(N_NODES + 255) / 256, 256>>>();
    deg_kernel<<<(N_EDGES / 4 + 255) / 256, 256>>>(edge_dst);
    scan_block_kernel<<<NSCAN, SCAN_BS>>>();
    finalize_kernel<<<(N_NODES + 255) / 256, 256>>>();
    scatter_cvt_kernel<<<SCAT_BLOCKS + CVT_BLOCKS, 256>>>(h, edge_src, edge_dst);

    {   // one warp per node
        int blocks = (N_NODES + 7) / 8;
        gather_kernel<<<blocks, 256>>>();
    }

    (void)cudaFuncSetAttribute(mma_gemm_kernel,
                               cudaFuncAttributeMaxDynamicSharedMemorySize,
                               SMEM_SZ);
    int tiles = (N_NODES + 127) / 128;   // 782
    mma_gemm_kernel<<<tiles, 256, SMEM_SZ>>>(W, b, out);
}